// round 2
// baseline (speedup 1.0000x reference)
#include <cuda_runtime.h>
#include <math.h>

// Problem dims
constexpr int B_ = 8;
constexpr int N_ = 1024;
constexpr int D_ = 256;

// ---------------- scratch (__device__ globals; no allocation) ----------------
__device__ float g_t[(size_t)B_ * N_ * D_];          // x @ U^T            [8192,256]
__device__ float g_xs[(size_t)B_ * N_ * 2 * D_];     // spectral outputs   [8192,512] cols k*256+j
__device__ float g_U12T[2 * D_ * D_];                // [512,256]: row k*256+j, col d = |S_k[d]|*U[d,j]
__device__ float g_pos[(size_t)N_ * N_];             // pos softmax        [1024,1024]
__device__ float g_scores[(size_t)B_ * 2 * N_ * N_]; // patch logits*scale [b,k,n,m]
__device__ float g_attn[(size_t)B_ * N_ * N_];       // selected attn rows
__device__ float g_yT[(size_t)B_ * D_ * N_];         // y transposed [b,j,m]

// ---------------- helpers ----------------
__device__ __forceinline__ float blk_max(float v, volatile float* sm) {
    #pragma unroll
    for (int o = 16; o > 0; o >>= 1) v = fmaxf(v, __shfl_xor_sync(0xffffffffu, v, o));
    if ((threadIdx.x & 31) == 0) sm[threadIdx.x >> 5] = v;
    __syncthreads();
    float r = sm[0];
    #pragma unroll
    for (int i = 1; i < 8; i++) r = fmaxf(r, sm[i]);
    __syncthreads();
    return r;
}

__device__ __forceinline__ float blk_sum(float v, volatile float* sm) {
    #pragma unroll
    for (int o = 16; o > 0; o >>= 1) v += __shfl_xor_sync(0xffffffffu, v, o);
    if ((threadIdx.x & 31) == 0) sm[threadIdx.x >> 5] = v;
    __syncthreads();
    float r = sm[0];
    #pragma unroll
    for (int i = 1; i < 8; i++) r += sm[i];
    __syncthreads();
    return r;
}

// ---------------- NT GEMM: C[m,n] = alpha * sum_k A[m,k]*Bm[n,k] ----------------
// BM=BN=64, BK=16, 256 threads, 4x4 micro-tile. All dims assumed divisible.
__device__ __forceinline__ void gemm_nt_64(
    const float* __restrict__ A, int lda,
    const float* __restrict__ Bm, int ldb,
    float* __restrict__ C, int ldc,
    int K, float alpha)
{
    constexpr int BM = 64, BN = 64, BK = 16, PAD = 4;
    __shared__ float As[BK][BM + PAD];
    __shared__ float Bs[BK][BN + PAD];

    const int tid = threadIdx.x;
    const int m0 = blockIdx.y * BM;
    const int n0 = blockIdx.x * BN;

    const int lr = tid >> 2;          // 0..63 : row within tile
    const int lc = (tid & 3) * 4;     // 0,4,8,12 : k offset (float4)
    const int tr = (tid >> 4) * 4;    // micro-tile row origin
    const int tc = (tid & 15) * 4;    // micro-tile col origin

    float acc[4][4] = {};

    const float* aP = A + (size_t)(m0 + lr) * lda + lc;
    const float* bP = Bm + (size_t)(n0 + lr) * ldb + lc;

    for (int kk = 0; kk < K; kk += BK) {
        float4 av = *(const float4*)(aP + kk);
        float4 bv = *(const float4*)(bP + kk);
        __syncthreads();
        As[lc + 0][lr] = av.x; As[lc + 1][lr] = av.y;
        As[lc + 2][lr] = av.z; As[lc + 3][lr] = av.w;
        Bs[lc + 0][lr] = bv.x; Bs[lc + 1][lr] = bv.y;
        Bs[lc + 2][lr] = bv.z; Bs[lc + 3][lr] = bv.w;
        __syncthreads();
        #pragma unroll
        for (int k2 = 0; k2 < BK; k2++) {
            float4 a = *(const float4*)&As[k2][tr];
            float4 b = *(const float4*)&Bs[k2][tc];
            acc[0][0] += a.x * b.x; acc[0][1] += a.x * b.y; acc[0][2] += a.x * b.z; acc[0][3] += a.x * b.w;
            acc[1][0] += a.y * b.x; acc[1][1] += a.y * b.y; acc[1][2] += a.y * b.z; acc[1][3] += a.y * b.w;
            acc[2][0] += a.z * b.x; acc[2][1] += a.z * b.y; acc[2][2] += a.z * b.z; acc[2][3] += a.z * b.w;
            acc[3][0] += a.w * b.x; acc[3][1] += a.w * b.y; acc[3][2] += a.w * b.z; acc[3][3] += a.w * b.w;
        }
    }

    #pragma unroll
    for (int i = 0; i < 4; i++) {
        float4 o;
        o.x = alpha * acc[i][0]; o.y = alpha * acc[i][1];
        o.z = alpha * acc[i][2]; o.w = alpha * acc[i][3];
        *(float4*)(C + (size_t)(m0 + tr + i) * ldc + n0 + tc) = o;
    }
}

// ---------------- kernels ----------------

// U12T[k*256+j][d] = |S_k[d]| * U[d][j]
__global__ void k_prep_u(const float* __restrict__ U,
                         const float* __restrict__ S1,
                         const float* __restrict__ S2) {
    int idx = blockIdx.x * blockDim.x + threadIdx.x;  // 512*256
    int r = idx >> 8;        // 0..511
    int d = idx & 255;
    int k = r >> 8;
    int j = r & 255;
    float s = fabsf(k ? S2[d] : S1[d]);
    g_U12T[idx] = s * U[d * 256 + j];
}

// yT[b][j][m] = y[b][m][j]
__global__ void k_transpose_y(const float* __restrict__ y) {
    __shared__ float tile[32][33];
    int b = blockIdx.z;
    int m0 = blockIdx.y * 32, j0 = blockIdx.x * 32;
    int tx = threadIdx.x, ty = threadIdx.y;   // 32 x 8
    #pragma unroll
    for (int i = ty; i < 32; i += 8)
        tile[i][tx] = y[((size_t)b * N_ + m0 + i) * D_ + j0 + tx];
    __syncthreads();
    #pragma unroll
    for (int i = ty; i < 32; i += 8)
        g_yT[((size_t)b * D_ + j0 + i) * N_ + m0 + tx] = tile[tx][i];
}

__global__ void k_gemm_t(const float* __restrict__ x, const float* __restrict__ U) {
    gemm_nt_64(x, D_, U, D_, g_t, D_, D_, 1.0f);
}

__global__ void k_gemm_xs() {
    gemm_nt_64(g_t, D_, g_U12T, D_, g_xs, 2 * D_, D_, 1.0f);
}

__global__ void k_gemm_scores(const float* __restrict__ y) {
    int z = blockIdx.z;           // b*2 + k
    int b = z >> 1, k = z & 1;
    gemm_nt_64(g_xs + (size_t)b * N_ * (2 * D_) + k * D_, 2 * D_,
               y + (size_t)b * N_ * D_, D_,
               g_scores + (size_t)z * N_ * N_, N_,
               D_, 0.0625f /* D^-0.5 */);
}

__global__ void k_gemm_out(float* __restrict__ out) {
    int b = blockIdx.z;
    gemm_nt_64(g_attn + (size_t)b * N_ * N_, N_,
               g_yT + (size_t)b * D_ * N_, N_,
               out + (size_t)b * N_ * D_, D_,
               N_, 1.0f);
}

// pos_score[n][m] = softmax_m( -|p_temp| * sum_c coords[n,m,c]*pos_emb[n,c] )
__global__ void k_pos(const float* __restrict__ coords,
                      const float* __restrict__ pos_emb,
                      const float* __restrict__ p_temp) {
    __shared__ float pe[6];
    __shared__ float sm[8];
    int n = blockIdx.x;
    int t = threadIdx.x;     // 256
    if (t < 6) pe[t] = pos_emb[n * 6 + t];
    __syncthreads();
    float pt = -fabsf(p_temp[0]);
    float lg[4];
    float lmax = -1e30f;
    #pragma unroll
    for (int i = 0; i < 4; i++) {
        int m = i * 256 + t;
        const float* c = coords + ((size_t)n * N_ + m) * 6;
        float acc = c[0] * pe[0] + c[1] * pe[1] + c[2] * pe[2]
                  + c[3] * pe[3] + c[4] * pe[4] + c[5] * pe[5];
        lg[i] = pt * acc;
        lmax = fmaxf(lmax, lg[i]);
    }
    float mx = blk_max(lmax, sm);
    float lsum = 0.f;
    #pragma unroll
    for (int i = 0; i < 4; i++) { lg[i] = __expf(lg[i] - mx); lsum += lg[i]; }
    float s = blk_sum(lsum, sm);
    float inv = 1.0f / s;
    #pragma unroll
    for (int i = 0; i < 4; i++)
        g_pos[(size_t)n * N_ + i * 256 + t] = lg[i] * inv;
}

// Per (b,n): softmax both branches, blend with pos, entropy, route, write selected row + heat.
__global__ void k_mix(const float* __restrict__ gating,
                      const float* __restrict__ h_temp,
                      float* __restrict__ heat) {
    __shared__ float sm[8];
    int bn = blockIdx.x;             // b*1024 + n
    int b = bn >> 10;
    int n = bn & (N_ - 1);
    int t = threadIdx.x;             // 256

    size_t base0 = ((size_t)(b * 2 + 0) * N_ + n) * N_;
    size_t base1 = ((size_t)(b * 2 + 1) * N_ + n) * N_;

    float s0[4], s1[4], pp[4];
    float lm0 = -1e30f, lm1 = -1e30f;
    #pragma unroll
    for (int i = 0; i < 4; i++) {
        int m = i * 256 + t;
        s0[i] = g_scores[base0 + m];
        s1[i] = g_scores[base1 + m];
        pp[i] = g_pos[(size_t)n * N_ + m];
        lm0 = fmaxf(lm0, s0[i]);
        lm1 = fmaxf(lm1, s1[i]);
    }
    float mx0 = blk_max(lm0, sm);
    float mx1 = blk_max(lm1, sm);

    float ls0 = 0.f, ls1 = 0.f;
    #pragma unroll
    for (int i = 0; i < 4; i++) {
        s0[i] = __expf(s0[i] - mx0); ls0 += s0[i];
        s1[i] = __expf(s1[i] - mx1); ls1 += s1[i];
    }
    float sum0 = blk_sum(ls0, sm);
    float sum1 = blk_sum(ls1, sm);
    float inv0 = 1.0f / sum0, inv1 = 1.0f / sum1;

    float g = 1.0f / (1.0f + __expf(-gating[0]));
    float og = 1.0f - g;

    float p0[4], p1[4];
    float le0 = 0.f, le1 = 0.f;
    #pragma unroll
    for (int i = 0; i < 4; i++) {
        p0[i] = og * s0[i] * inv0 + g * pp[i];
        p1[i] = og * s1[i] * inv1 + g * pp[i];
        le0 -= p0[i] * __logf(p0[i] + 1e-8f);
        le1 -= p1[i] * __logf(p1[i] + 1e-8f);
    }
    float ent0 = blk_sum(le0, sm);
    float ent1 = blk_sum(le1, sm);

    float ht = h_temp[0];
    float hm0 = 2.0f - 2.0f / (1.0f + __expf(-ht * ent0));
    float hm1 = 2.0f - 2.0f / (1.0f + __expf(-ht * ent1));
    int sel = (hm0 >= hm1) ? 0 : 1;

    #pragma unroll
    for (int i = 0; i < 4; i++)
        g_attn[(size_t)bn * N_ + i * 256 + t] = sel ? p1[i] : p0[i];

    if (t == 0) heat[bn] = sel ? hm1 : hm0;
}

// ---------------- launch ----------------
extern "C" void kernel_launch(void* const* d_in, const int* in_sizes, int n_in,
                              void* d_out, int out_size) {
    const float* x       = (const float*)d_in[0];
    const float* y       = (const float*)d_in[1];
    const float* coords  = (const float*)d_in[2];
    const float* U       = (const float*)d_in[3];
    const float* S1      = (const float*)d_in[4];
    const float* S2      = (const float*)d_in[5];
    const float* gating  = (const float*)d_in[6];
    const float* h_temp  = (const float*)d_in[7];
    const float* p_temp  = (const float*)d_in[8];
    const float* pos_emb = (const float*)d_in[9];

    float* out  = (float*)d_out;
    float* heat = out + (size_t)B_ * N_ * D_;

    // prep
    k_prep_u<<<(2 * D_ * D_) / 256, 256>>>(U, S1, S2);
    k_transpose_y<<<dim3(D_ / 32, N_ / 32, B_), dim3(32, 8)>>>(y);
    k_pos<<<N_, 256>>>(coords, pos_emb, p_temp);

    // spectral: t = x@U^T ; xs = t@U12T^T
    k_gemm_t<<<dim3(D_ / 64, (B_ * N_) / 64), 256>>>(x, U);
    k_gemm_xs<<<dim3((2 * D_) / 64, (B_ * N_) / 64), 256>>>();

    // patch logits (scaled)
    k_gemm_scores<<<dim3(N_ / 64, N_ / 64, B_ * 2), 256>>>(y);

    // softmax/blend/entropy/route
    k_mix<<<B_ * N_, 256>>>(gating, h_temp, heat);

    // out = attn_sel @ y
    k_gemm_out<<<dim3(D_ / 64, N_ / 64, B_), 256>>>(out);
}

// round 3
// speedup vs baseline: 1.1810x; 1.1810x over previous
#include <cuda_runtime.h>
#include <math.h>
#include <stdint.h>

// Problem dims
constexpr int B_ = 8;
constexpr int N_ = 1024;
constexpr int D_ = 256;

// ---------------- scratch (__device__ globals; no allocation) ----------------
__device__ float g_t[(size_t)B_ * N_ * D_];          // x @ U^T            [8192,256]
__device__ float g_xs[(size_t)B_ * N_ * 2 * D_];     // spectral outputs   [8192,512]
__device__ float g_U12T[2 * D_ * D_];                // [512,256]
__device__ float g_pos[(size_t)N_ * N_];             // pos softmax
__device__ float g_scores[(size_t)B_ * 2 * N_ * N_]; // patch logits*scale
__device__ float g_attn[(size_t)B_ * N_ * N_];       // selected attn rows
__device__ float g_yT[(size_t)B_ * D_ * N_];         // y transposed

// ---------------- small helpers ----------------
__device__ __forceinline__ float blk_max(float v, volatile float* sm) {
    #pragma unroll
    for (int o = 16; o > 0; o >>= 1) v = fmaxf(v, __shfl_xor_sync(0xffffffffu, v, o));
    if ((threadIdx.x & 31) == 0) sm[threadIdx.x >> 5] = v;
    __syncthreads();
    float r = sm[0];
    #pragma unroll
    for (int i = 1; i < 8; i++) r = fmaxf(r, sm[i]);
    __syncthreads();
    return r;
}
__device__ __forceinline__ float blk_sum(float v, volatile float* sm) {
    #pragma unroll
    for (int o = 16; o > 0; o >>= 1) v += __shfl_xor_sync(0xffffffffu, v, o);
    if ((threadIdx.x & 31) == 0) sm[threadIdx.x >> 5] = v;
    __syncthreads();
    float r = sm[0];
    #pragma unroll
    for (int i = 1; i < 8; i++) r += sm[i];
    __syncthreads();
    return r;
}

// ---------------- tensor-core primitives ----------------
__device__ __forceinline__ uint32_t smaddr(const void* p) {
    return (uint32_t)__cvta_generic_to_shared(p);
}
__device__ __forceinline__ void ldm_x4(uint32_t* r, uint32_t addr) {
    asm volatile("ldmatrix.sync.aligned.m8n8.x4.shared.b16 {%0,%1,%2,%3}, [%4];"
                 : "=r"(r[0]), "=r"(r[1]), "=r"(r[2]), "=r"(r[3]) : "r"(addr));
}
__device__ __forceinline__ void mma_tf32(float* c, const uint32_t* a, const uint32_t* b) {
    asm volatile("mma.sync.aligned.m16n8k8.row.col.f32.tf32.tf32.f32 "
                 "{%0,%1,%2,%3}, {%4,%5,%6,%7}, {%8,%9}, {%0,%1,%2,%3};"
                 : "+f"(c[0]), "+f"(c[1]), "+f"(c[2]), "+f"(c[3])
                 : "r"(a[0]), "r"(a[1]), "r"(a[2]), "r"(a[3]), "r"(b[0]), "r"(b[1]));
}
__device__ __forceinline__ uint32_t f2tf32(float x) {
    uint32_t u; asm("cvt.rna.tf32.f32 %0, %1;" : "=r"(u) : "f"(x)); return u;
}
__device__ __forceinline__ void split_store(float* hi, float* lo, int off, float4 v) {
    float xs[4] = {v.x, v.y, v.z, v.w};
    #pragma unroll
    for (int i = 0; i < 4; i++) {
        uint32_t h = f2tf32(xs[i]);
        float hf = __uint_as_float(h);
        hi[off + i] = hf;
        lo[off + i] = __uint_as_float(f2tf32(xs[i] - hf));
    }
}

// ---------------- NT GEMM via 3xTF32: C[m,n] = alpha * sum_k A[m,k]*Bm[n,k] ----
// Block 128x128, BK=16, 256 threads (8 warps, 4x2 of 32x64 warp tiles).
constexpr int RS = 20;  // smem row stride (floats); 80B -> conflict-free ldmatrix

__device__ __forceinline__ void gemm_tc(
    const float* __restrict__ A, int lda,
    const float* __restrict__ Bm, int ldb,
    float* __restrict__ C, int ldc,
    int K, float alpha)
{
    __shared__ float sA_hi[128 * RS];
    __shared__ float sA_lo[128 * RS];
    __shared__ float sB_hi[128 * RS];
    __shared__ float sB_lo[128 * RS];

    const int tid = threadIdx.x;
    const int lane = tid & 31;
    const int warp = tid >> 5;
    const int wm = (warp & 3) * 32;   // warp row origin
    const int wn = (warp >> 2) * 64;  // warp col origin
    const int m0 = blockIdx.y * 128;
    const int n0 = blockIdx.x * 128;

    // loader mapping: thread -> (row, 8 consecutive k)
    const int lr  = tid >> 1;
    const int lkq = (tid & 1) * 8;
    const float* aP = A  + (size_t)(m0 + lr) * lda + lkq;
    const float* bP = Bm + (size_t)(n0 + lr) * ldb + lkq;

    float4 ra0 = *(const float4*)(aP);
    float4 ra1 = *(const float4*)(aP + 4);
    float4 rb0 = *(const float4*)(bP);
    float4 rb1 = *(const float4*)(bP + 4);

    float acc[2][8][4];
    #pragma unroll
    for (int f = 0; f < 2; f++)
        #pragma unroll
        for (int q = 0; q < 8; q++)
            #pragma unroll
            for (int i = 0; i < 4; i++) acc[f][q][i] = 0.0f;

    // ldmatrix per-lane base addresses
    const int mat = lane >> 3, idx = lane & 7;
    const int arow = wm + (mat & 1) * 8 + idx;   // + f*16
    const int acol = (mat >> 1) * 4;             // + k8*8
    const uint32_t aHiB = smaddr(&sA_hi[arow * RS + acol]);
    const uint32_t aLoB = smaddr(&sA_lo[arow * RS + acol]);
    const int brow = wn + (mat >> 1) * 8 + idx;  // + p*16
    const int bcol = (mat & 1) * 4;
    const uint32_t bHiB = smaddr(&sB_hi[brow * RS + bcol]);
    const uint32_t bLoB = smaddr(&sB_lo[brow * RS + bcol]);

    const int ktiles = K >> 4;
    for (int kt = 0; kt < ktiles; kt++) {
        __syncthreads();
        const int soff = lr * RS + lkq;
        split_store(sA_hi, sA_lo, soff, ra0);
        split_store(sA_hi, sA_lo, soff + 4, ra1);
        split_store(sB_hi, sB_lo, soff, rb0);
        split_store(sB_hi, sB_lo, soff + 4, rb1);
        __syncthreads();

        if (kt + 1 < ktiles) {
            const float* a2 = aP + (size_t)(kt + 1) * 16;
            const float* b2 = bP + (size_t)(kt + 1) * 16;
            ra0 = *(const float4*)(a2);
            ra1 = *(const float4*)(a2 + 4);
            rb0 = *(const float4*)(b2);
            rb1 = *(const float4*)(b2 + 4);
        }

        #pragma unroll
        for (int k8 = 0; k8 < 2; k8++) {
            const uint32_t koff = k8 * 8 * 4;  // 8 floats
            uint32_t ah[2][4], al[2][4];
            ldm_x4(ah[0], aHiB + koff);
            ldm_x4(ah[1], aHiB + 16 * RS * 4 + koff);
            ldm_x4(al[0], aLoB + koff);
            ldm_x4(al[1], aLoB + 16 * RS * 4 + koff);
            #pragma unroll
            for (int p = 0; p < 4; p++) {
                uint32_t bh[4], bl[4];
                ldm_x4(bh, bHiB + p * 16 * RS * 4 + koff);
                ldm_x4(bl, bLoB + p * 16 * RS * 4 + koff);
                #pragma unroll
                for (int f = 0; f < 2; f++) {
                    mma_tf32(acc[f][2 * p],     ah[f], bh);
                    mma_tf32(acc[f][2 * p + 1], ah[f], bh + 2);
                    mma_tf32(acc[f][2 * p],     ah[f], bl);
                    mma_tf32(acc[f][2 * p + 1], ah[f], bl + 2);
                    mma_tf32(acc[f][2 * p],     al[f], bh);
                    mma_tf32(acc[f][2 * p + 1], al[f], bh + 2);
                }
            }
        }
    }

    // epilogue
    const int g = lane >> 2, tig = lane & 3;
    #pragma unroll
    for (int f = 0; f < 2; f++) {
        #pragma unroll
        for (int q = 0; q < 8; q++) {
            const int r = m0 + wm + f * 16 + g;
            const int c = n0 + wn + q * 8 + tig * 2;
            float2 v0 = {alpha * acc[f][q][0], alpha * acc[f][q][1]};
            float2 v1 = {alpha * acc[f][q][2], alpha * acc[f][q][3]};
            *(float2*)(C + (size_t)r * ldc + c) = v0;
            *(float2*)(C + (size_t)(r + 8) * ldc + c) = v1;
        }
    }
}

// ---------------- kernels ----------------
__global__ void k_prep_u(const float* __restrict__ U,
                         const float* __restrict__ S1,
                         const float* __restrict__ S2) {
    int idxx = blockIdx.x * blockDim.x + threadIdx.x;
    int r = idxx >> 8;
    int d = idxx & 255;
    int k = r >> 8;
    int j = r & 255;
    float s = fabsf(k ? S2[d] : S1[d]);
    g_U12T[idxx] = s * U[d * 256 + j];
}

__global__ void k_transpose_y(const float* __restrict__ y) {
    __shared__ float tile[32][33];
    int b = blockIdx.z;
    int m0 = blockIdx.y * 32, j0 = blockIdx.x * 32;
    int tx = threadIdx.x, ty = threadIdx.y;
    #pragma unroll
    for (int i = ty; i < 32; i += 8)
        tile[i][tx] = y[((size_t)b * N_ + m0 + i) * D_ + j0 + tx];
    __syncthreads();
    #pragma unroll
    for (int i = ty; i < 32; i += 8)
        g_yT[((size_t)b * D_ + j0 + i) * N_ + m0 + tx] = tile[tx][i];
}

__global__ void __launch_bounds__(256, 2)
k_gemm_t(const float* __restrict__ x, const float* __restrict__ U) {
    gemm_tc(x, D_, U, D_, g_t, D_, D_, 1.0f);
}

__global__ void __launch_bounds__(256, 2)
k_gemm_xs() {
    gemm_tc(g_t, D_, g_U12T, D_, g_xs, 2 * D_, D_, 1.0f);
}

__global__ void __launch_bounds__(256, 2)
k_gemm_scores(const float* __restrict__ y) {
    int z = blockIdx.z;
    int b = z >> 1, k = z & 1;
    gemm_tc(g_xs + (size_t)b * N_ * (2 * D_) + k * D_, 2 * D_,
            y + (size_t)b * N_ * D_, D_,
            g_scores + (size_t)z * N_ * N_, N_,
            D_, 0.0625f);
}

__global__ void __launch_bounds__(256, 2)
k_gemm_out(float* __restrict__ out) {
    int b = blockIdx.z;
    gemm_tc(g_attn + (size_t)b * N_ * N_, N_,
            g_yT + (size_t)b * D_ * N_, N_,
            out + (size_t)b * N_ * D_, D_,
            N_, 1.0f);
}

__global__ void k_pos(const float* __restrict__ coords,
                      const float* __restrict__ pos_emb,
                      const float* __restrict__ p_temp) {
    __shared__ float pe[6];
    __shared__ float sm[8];
    int n = blockIdx.x;
    int t = threadIdx.x;
    if (t < 6) pe[t] = pos_emb[n * 6 + t];
    __syncthreads();
    float pt = -fabsf(p_temp[0]);
    float lg[4];
    float lmax = -1e30f;
    #pragma unroll
    for (int i = 0; i < 4; i++) {
        int m = i * 256 + t;
        const float* c = coords + ((size_t)n * N_ + m) * 6;
        float a = c[0] * pe[0] + c[1] * pe[1] + c[2] * pe[2]
                + c[3] * pe[3] + c[4] * pe[4] + c[5] * pe[5];
        lg[i] = pt * a;
        lmax = fmaxf(lmax, lg[i]);
    }
    float mx = blk_max(lmax, sm);
    float lsum = 0.f;
    #pragma unroll
    for (int i = 0; i < 4; i++) { lg[i] = __expf(lg[i] - mx); lsum += lg[i]; }
    float s = blk_sum(lsum, sm);
    float inv = 1.0f / s;
    #pragma unroll
    for (int i = 0; i < 4; i++)
        g_pos[(size_t)n * N_ + i * 256 + t] = lg[i] * inv;
}

__global__ void k_mix(const float* __restrict__ gating,
                      const float* __restrict__ h_temp,
                      float* __restrict__ heat) {
    __shared__ float sm[8];
    int bn = blockIdx.x;
    int b = bn >> 10;
    int n = bn & (N_ - 1);
    int t = threadIdx.x;

    size_t base0 = ((size_t)(b * 2 + 0) * N_ + n) * N_;
    size_t base1 = ((size_t)(b * 2 + 1) * N_ + n) * N_;

    float s0[4], s1[4], pp[4];
    float lm0 = -1e30f, lm1 = -1e30f;
    #pragma unroll
    for (int i = 0; i < 4; i++) {
        int m = i * 256 + t;
        s0[i] = g_scores[base0 + m];
        s1[i] = g_scores[base1 + m];
        pp[i] = g_pos[(size_t)n * N_ + m];
        lm0 = fmaxf(lm0, s0[i]);
        lm1 = fmaxf(lm1, s1[i]);
    }
    float mx0 = blk_max(lm0, sm);
    float mx1 = blk_max(lm1, sm);

    float ls0 = 0.f, ls1 = 0.f;
    #pragma unroll
    for (int i = 0; i < 4; i++) {
        s0[i] = __expf(s0[i] - mx0); ls0 += s0[i];
        s1[i] = __expf(s1[i] - mx1); ls1 += s1[i];
    }
    float sum0 = blk_sum(ls0, sm);
    float sum1 = blk_sum(ls1, sm);
    float inv0 = 1.0f / sum0, inv1 = 1.0f / sum1;

    float g = 1.0f / (1.0f + __expf(-gating[0]));
    float og = 1.0f - g;

    float p0[4], p1[4];
    float le0 = 0.f, le1 = 0.f;
    #pragma unroll
    for (int i = 0; i < 4; i++) {
        p0[i] = og * s0[i] * inv0 + g * pp[i];
        p1[i] = og * s1[i] * inv1 + g * pp[i];
        le0 -= p0[i] * __logf(p0[i] + 1e-8f);
        le1 -= p1[i] * __logf(p1[i] + 1e-8f);
    }
    float ent0 = blk_sum(le0, sm);
    float ent1 = blk_sum(le1, sm);

    float ht = h_temp[0];
    float hm0 = 2.0f - 2.0f / (1.0f + __expf(-ht * ent0));
    float hm1 = 2.0f - 2.0f / (1.0f + __expf(-ht * ent1));
    int sel = (hm0 >= hm1) ? 0 : 1;

    #pragma unroll
    for (int i = 0; i < 4; i++)
        g_attn[(size_t)bn * N_ + i * 256 + t] = sel ? p1[i] : p0[i];

    if (t == 0) heat[bn] = sel ? hm1 : hm0;
}

// ---------------- launch ----------------
extern "C" void kernel_launch(void* const* d_in, const int* in_sizes, int n_in,
                              void* d_out, int out_size) {
    const float* x       = (const float*)d_in[0];
    const float* y       = (const float*)d_in[1];
    const float* coords  = (const float*)d_in[2];
    const float* U       = (const float*)d_in[3];
    const float* S1      = (const float*)d_in[4];
    const float* S2      = (const float*)d_in[5];
    const float* gating  = (const float*)d_in[6];
    const float* h_temp  = (const float*)d_in[7];
    const float* p_temp  = (const float*)d_in[8];
    const float* pos_emb = (const float*)d_in[9];

    float* out  = (float*)d_out;
    float* heat = out + (size_t)B_ * N_ * D_;

    k_prep_u<<<(2 * D_ * D_) / 256, 256>>>(U, S1, S2);
    k_transpose_y<<<dim3(D_ / 32, N_ / 32, B_), dim3(32, 8)>>>(y);
    k_pos<<<N_, 256>>>(coords, pos_emb, p_temp);

    k_gemm_t<<<dim3(D_ / 128, (B_ * N_) / 128), 256>>>(x, U);
    k_gemm_xs<<<dim3((2 * D_) / 128, (B_ * N_) / 128), 256>>>();
    k_gemm_scores<<<dim3(N_ / 128, N_ / 128, B_ * 2), 256>>>(y);

    k_mix<<<B_ * N_, 256>>>(gating, h_temp, heat);

    k_gemm_out<<<dim3(D_ / 128, N_ / 128, B_), 256>>>(out);
}

// round 4
// speedup vs baseline: 1.4233x; 1.2052x over previous
#include <cuda_runtime.h>
#include <math.h>
#include <stdint.h>

// Problem dims
constexpr int B_ = 8;
constexpr int N_ = 1024;
constexpr int D_ = 256;

// ---------------- scratch (__device__ globals; no allocation) ----------------
__device__ float g_t[(size_t)B_ * N_ * D_];
__device__ float g_xs[(size_t)B_ * N_ * 2 * D_];
__device__ float g_U12T[2 * D_ * D_];
__device__ float g_pos[(size_t)N_ * N_];
__device__ float g_scores[(size_t)B_ * 2 * N_ * N_];
__device__ float g_attn[(size_t)B_ * N_ * N_];
__device__ float g_yT[(size_t)B_ * D_ * N_];

// ---------------- small helpers ----------------
__device__ __forceinline__ float blk_max(float v, volatile float* sm) {
    #pragma unroll
    for (int o = 16; o > 0; o >>= 1) v = fmaxf(v, __shfl_xor_sync(0xffffffffu, v, o));
    if ((threadIdx.x & 31) == 0) sm[threadIdx.x >> 5] = v;
    __syncthreads();
    float r = sm[0];
    #pragma unroll
    for (int i = 1; i < 8; i++) r = fmaxf(r, sm[i]);
    __syncthreads();
    return r;
}
__device__ __forceinline__ float blk_sum(float v, volatile float* sm) {
    #pragma unroll
    for (int o = 16; o > 0; o >>= 1) v += __shfl_xor_sync(0xffffffffu, v, o);
    if ((threadIdx.x & 31) == 0) sm[threadIdx.x >> 5] = v;
    __syncthreads();
    float r = sm[0];
    #pragma unroll
    for (int i = 1; i < 8; i++) r += sm[i];
    __syncthreads();
    return r;
}

// ---------------- tensor-core primitives ----------------
__device__ __forceinline__ uint32_t smaddr(const void* p) {
    return (uint32_t)__cvta_generic_to_shared(p);
}
__device__ __forceinline__ void ldm_x4(uint32_t* r, uint32_t addr) {
    asm volatile("ldmatrix.sync.aligned.m8n8.x4.shared.b16 {%0,%1,%2,%3}, [%4];"
                 : "=r"(r[0]), "=r"(r[1]), "=r"(r[2]), "=r"(r[3]) : "r"(addr));
}
__device__ __forceinline__ void mma_tf32(float* c, const uint32_t* a, const uint32_t* b) {
    asm volatile("mma.sync.aligned.m16n8k8.row.col.f32.tf32.tf32.f32 "
                 "{%0,%1,%2,%3}, {%4,%5,%6,%7}, {%8,%9}, {%0,%1,%2,%3};"
                 : "+f"(c[0]), "+f"(c[1]), "+f"(c[2]), "+f"(c[3])
                 : "r"(a[0]), "r"(a[1]), "r"(a[2]), "r"(a[3]), "r"(b[0]), "r"(b[1]));
}
__device__ __forceinline__ uint32_t f2tf32(float x) {
    uint32_t u; asm("cvt.rna.tf32.f32 %0, %1;" : "=r"(u) : "f"(x)); return u;
}
__device__ __forceinline__ void split_store(float* hi, float* lo, int off, float4 v) {
    float xs[4] = {v.x, v.y, v.z, v.w};
    #pragma unroll
    for (int i = 0; i < 4; i++) {
        uint32_t h = f2tf32(xs[i]);
        float hf = __uint_as_float(h);
        hi[off + i] = hf;
        lo[off + i] = __uint_as_float(f2tf32(xs[i] - hf));
    }
}

// ---------------- NT GEMM via 3xTF32, double-buffered ------------------------
// Block 128xBN, BK=16, 256 threads. BN=128: 8 warps of 32x64. BN=64: 32x32.
constexpr int RS = 20;  // smem row stride (floats); 80B -> conflict-free ldmatrix

template <int BN>
__device__ __forceinline__ void gemm_tc(
    const float* __restrict__ A, int lda,
    const float* __restrict__ Bm, int ldb,
    float* __restrict__ C, int ldc,
    int K, float alpha)
{
    constexpr int BM = 128, BK = 16;
    constexpr int ASZ = BM * RS;           // floats per A plane
    constexpr int BSZ = BN * RS;           // floats per B plane
    constexpr int STG = 2 * ASZ + 2 * BSZ; // floats per stage
    constexpr int WN = BN / 2;
    constexpr int nP = BN / 32;            // 16-col B groups per warp

    extern __shared__ float smem[];

    const int tid = threadIdx.x;
    const int lane = tid & 31;
    const int warp = tid >> 5;
    const int wm = (warp & 3) * 32;
    const int wn = (warp >> 2) * WN;
    const int m0 = blockIdx.y * BM;
    const int n0 = blockIdx.x * BN;

    // loaders: 8 consecutive k floats per thread
    const int alr = tid >> 1, alk = (tid & 1) * 8;
    const float* aP = A + (size_t)(m0 + alr) * lda + alk;
    const bool bAct = (tid < BN * 2);
    const int blr = tid >> 1, blk2 = (tid & 1) * 8;
    const float* bP = Bm + (size_t)(n0 + blr) * ldb + blk2;

    float4 ra0, ra1, rb0 = make_float4(0, 0, 0, 0), rb1 = make_float4(0, 0, 0, 0);
    ra0 = *(const float4*)(aP);
    ra1 = *(const float4*)(aP + 4);
    if (bAct) { rb0 = *(const float4*)(bP); rb1 = *(const float4*)(bP + 4); }

    float acc[2][2 * nP][4] = {};

    // ldmatrix per-lane base addresses (stage 0)
    const int mat = lane >> 3, idx = lane & 7;
    const int arow = wm + (mat & 1) * 8 + idx;
    const int acol = (mat >> 1) * 4;
    const int brow = wn + (mat >> 1) * 8 + idx;
    const int bcol = (mat & 1) * 4;
    const uint32_t aHiB = smaddr(&smem[arow * RS + acol]);
    const uint32_t aLoB = aHiB + ASZ * 4;
    const uint32_t bHiB = smaddr(&smem[2 * ASZ + brow * RS + bcol]);
    const uint32_t bLoB = bHiB + BSZ * 4;

    const int sAoff = alr * RS + alk;
    const int sBoff = blr * RS + blk2;

    // prologue: tile 0 -> stage 0
    split_store(smem, smem + ASZ, sAoff, ra0);
    split_store(smem, smem + ASZ, sAoff + 4, ra1);
    if (bAct) {
        split_store(smem + 2 * ASZ, smem + 2 * ASZ + BSZ, sBoff, rb0);
        split_store(smem + 2 * ASZ, smem + 2 * ASZ + BSZ, sBoff + 4, rb1);
    }
    __syncthreads();

    const int ktiles = K >> 4;
    for (int kt = 0; kt < ktiles; kt++) {
        const int st = kt & 1;
        const uint32_t so = (uint32_t)st * STG * 4;

        // prefetch next tile into regs (latency hidden under MMAs below)
        if (kt + 1 < ktiles) {
            const float* a2 = aP + (size_t)(kt + 1) * BK;
            ra0 = *(const float4*)(a2);
            ra1 = *(const float4*)(a2 + 4);
            if (bAct) {
                const float* b2 = bP + (size_t)(kt + 1) * BK;
                rb0 = *(const float4*)(b2);
                rb1 = *(const float4*)(b2 + 4);
            }
        }

        // compute tile kt from stage st
        #pragma unroll
        for (int k8 = 0; k8 < 2; k8++) {
            const uint32_t koff = k8 * 32;
            uint32_t ah[2][4], al[2][4];
            ldm_x4(ah[0], aHiB + so + koff);
            ldm_x4(ah[1], aHiB + so + 16 * RS * 4 + koff);
            ldm_x4(al[0], aLoB + so + koff);
            ldm_x4(al[1], aLoB + so + 16 * RS * 4 + koff);
            #pragma unroll
            for (int p = 0; p < nP; p++) {
                uint32_t bh[4], bl[4];
                ldm_x4(bh, bHiB + so + p * 16 * RS * 4 + koff);
                ldm_x4(bl, bLoB + so + p * 16 * RS * 4 + koff);
                #pragma unroll
                for (int f = 0; f < 2; f++) {
                    mma_tf32(acc[f][2 * p],     ah[f], bh);
                    mma_tf32(acc[f][2 * p + 1], ah[f], bh + 2);
                    mma_tf32(acc[f][2 * p],     ah[f], bl);
                    mma_tf32(acc[f][2 * p + 1], ah[f], bl + 2);
                    mma_tf32(acc[f][2 * p],     al[f], bh);
                    mma_tf32(acc[f][2 * p + 1], al[f], bh + 2);
                }
            }
        }

        // store tile kt+1 into the other stage; overlaps MMAs (no barrier between)
        if (kt + 1 < ktiles) {
            float* d = smem + (st ^ 1) * STG;
            split_store(d, d + ASZ, sAoff, ra0);
            split_store(d, d + ASZ, sAoff + 4, ra1);
            if (bAct) {
                split_store(d + 2 * ASZ, d + 2 * ASZ + BSZ, sBoff, rb0);
                split_store(d + 2 * ASZ, d + 2 * ASZ + BSZ, sBoff + 4, rb1);
            }
        }
        __syncthreads();  // single barrier per K-tile
    }

    // epilogue
    const int g = lane >> 2, tig = lane & 3;
    #pragma unroll
    for (int f = 0; f < 2; f++) {
        #pragma unroll
        for (int q = 0; q < 2 * nP; q++) {
            const int r = m0 + wm + f * 16 + g;
            const int c = n0 + wn + q * 8 + tig * 2;
            float2 v0 = {alpha * acc[f][q][0], alpha * acc[f][q][1]};
            float2 v1 = {alpha * acc[f][q][2], alpha * acc[f][q][3]};
            *(float2*)(C + (size_t)r * ldc + c) = v0;
            *(float2*)(C + (size_t)(r + 8) * ldc + c) = v1;
        }
    }
}

// smem sizes (bytes)
constexpr int SMEM128 = 2 * (2 * 128 * RS + 2 * 128 * RS) * 4;  // 81920
constexpr int SMEM64  = 2 * (2 * 128 * RS + 2 * 64 * RS) * 4;   // 61440

// ---------------- kernels ----------------
__global__ void k_prep_u(const float* __restrict__ U,
                         const float* __restrict__ S1,
                         const float* __restrict__ S2) {
    int idxx = blockIdx.x * blockDim.x + threadIdx.x;
    int r = idxx >> 8;
    int d = idxx & 255;
    int k = r >> 8;
    int j = r & 255;
    float s = fabsf(k ? S2[d] : S1[d]);
    g_U12T[idxx] = s * U[d * 256 + j];
}

__global__ void k_transpose_y(const float* __restrict__ y) {
    __shared__ float tile[32][33];
    int b = blockIdx.z;
    int m0 = blockIdx.y * 32, j0 = blockIdx.x * 32;
    int tx = threadIdx.x, ty = threadIdx.y;
    #pragma unroll
    for (int i = ty; i < 32; i += 8)
        tile[i][tx] = y[((size_t)b * N_ + m0 + i) * D_ + j0 + tx];
    __syncthreads();
    #pragma unroll
    for (int i = ty; i < 32; i += 8)
        g_yT[((size_t)b * D_ + j0 + i) * N_ + m0 + tx] = tile[tx][i];
}

__global__ void __launch_bounds__(256, 2)
k_gemm_t(const float* __restrict__ x, const float* __restrict__ U) {
    gemm_tc<64>(x, D_, U, D_, g_t, D_, D_, 1.0f);
}

__global__ void __launch_bounds__(256, 2)
k_gemm_xs() {
    gemm_tc<128>(g_t, D_, g_U12T, D_, g_xs, 2 * D_, D_, 1.0f);
}

__global__ void __launch_bounds__(256, 2)
k_gemm_scores(const float* __restrict__ y) {
    int z = blockIdx.z;
    int b = z >> 1, k = z & 1;
    gemm_tc<128>(g_xs + (size_t)b * N_ * (2 * D_) + k * D_, 2 * D_,
                 y + (size_t)b * N_ * D_, D_,
                 g_scores + (size_t)z * N_ * N_, N_,
                 D_, 0.0625f);
}

__global__ void __launch_bounds__(256, 2)
k_gemm_out(float* __restrict__ out) {
    int b = blockIdx.z;
    gemm_tc<64>(g_attn + (size_t)b * N_ * N_, N_,
                g_yT + (size_t)b * D_ * N_, N_,
                out + (size_t)b * N_ * D_, D_,
                N_, 1.0f);
}

__global__ void k_pos(const float* __restrict__ coords,
                      const float* __restrict__ pos_emb,
                      const float* __restrict__ p_temp) {
    __shared__ float pe[6];
    __shared__ float sm[8];
    int n = blockIdx.x;
    int t = threadIdx.x;
    if (t < 6) pe[t] = pos_emb[n * 6 + t];
    __syncthreads();
    float pt = -fabsf(p_temp[0]);
    float lg[4];
    float lmax = -1e30f;
    #pragma unroll
    for (int i = 0; i < 4; i++) {
        int m = i * 256 + t;
        const float* c = coords + ((size_t)n * N_ + m) * 6;
        float a = c[0] * pe[0] + c[1] * pe[1] + c[2] * pe[2]
                + c[3] * pe[3] + c[4] * pe[4] + c[5] * pe[5];
        lg[i] = pt * a;
        lmax = fmaxf(lmax, lg[i]);
    }
    float mx = blk_max(lmax, sm);
    float lsum = 0.f;
    #pragma unroll
    for (int i = 0; i < 4; i++) { lg[i] = __expf(lg[i] - mx); lsum += lg[i]; }
    float s = blk_sum(lsum, sm);
    float inv = 1.0f / s;
    #pragma unroll
    for (int i = 0; i < 4; i++)
        g_pos[(size_t)n * N_ + i * 256 + t] = lg[i] * inv;
}

__global__ void k_mix(const float* __restrict__ gating,
                      const float* __restrict__ h_temp,
                      float* __restrict__ heat) {
    __shared__ float sm[8];
    int bn = blockIdx.x;
    int b = bn >> 10;
    int n = bn & (N_ - 1);
    int t = threadIdx.x;

    size_t base0 = ((size_t)(b * 2 + 0) * N_ + n) * N_;
    size_t base1 = ((size_t)(b * 2 + 1) * N_ + n) * N_;

    float s0[4], s1[4], pp[4];
    float lm0 = -1e30f, lm1 = -1e30f;
    #pragma unroll
    for (int i = 0; i < 4; i++) {
        int m = i * 256 + t;
        s0[i] = g_scores[base0 + m];
        s1[i] = g_scores[base1 + m];
        pp[i] = g_pos[(size_t)n * N_ + m];
        lm0 = fmaxf(lm0, s0[i]);
        lm1 = fmaxf(lm1, s1[i]);
    }
    float mx0 = blk_max(lm0, sm);
    float mx1 = blk_max(lm1, sm);

    float ls0 = 0.f, ls1 = 0.f;
    #pragma unroll
    for (int i = 0; i < 4; i++) {
        s0[i] = __expf(s0[i] - mx0); ls0 += s0[i];
        s1[i] = __expf(s1[i] - mx1); ls1 += s1[i];
    }
    float sum0 = blk_sum(ls0, sm);
    float sum1 = blk_sum(ls1, sm);
    float inv0 = 1.0f / sum0, inv1 = 1.0f / sum1;

    float g = 1.0f / (1.0f + __expf(-gating[0]));
    float og = 1.0f - g;

    float p0[4], p1[4];
    float le0 = 0.f, le1 = 0.f;
    #pragma unroll
    for (int i = 0; i < 4; i++) {
        p0[i] = og * s0[i] * inv0 + g * pp[i];
        p1[i] = og * s1[i] * inv1 + g * pp[i];
        le0 -= p0[i] * __logf(p0[i] + 1e-8f);
        le1 -= p1[i] * __logf(p1[i] + 1e-8f);
    }
    float ent0 = blk_sum(le0, sm);
    float ent1 = blk_sum(le1, sm);

    float ht = h_temp[0];
    float hm0 = 2.0f - 2.0f / (1.0f + __expf(-ht * ent0));
    float hm1 = 2.0f - 2.0f / (1.0f + __expf(-ht * ent1));
    int sel = (hm0 >= hm1) ? 0 : 1;

    #pragma unroll
    for (int i = 0; i < 4; i++)
        g_attn[(size_t)bn * N_ + i * 256 + t] = sel ? p1[i] : p0[i];

    if (t == 0) heat[bn] = sel ? hm1 : hm0;
}

// ---------------- launch ----------------
extern "C" void kernel_launch(void* const* d_in, const int* in_sizes, int n_in,
                              void* d_out, int out_size) {
    const float* x       = (const float*)d_in[0];
    const float* y       = (const float*)d_in[1];
    const float* coords  = (const float*)d_in[2];
    const float* U       = (const float*)d_in[3];
    const float* S1      = (const float*)d_in[4];
    const float* S2      = (const float*)d_in[5];
    const float* gating  = (const float*)d_in[6];
    const float* h_temp  = (const float*)d_in[7];
    const float* p_temp  = (const float*)d_in[8];
    const float* pos_emb = (const float*)d_in[9];

    float* out  = (float*)d_out;
    float* heat = out + (size_t)B_ * N_ * D_;

    // opt-in to >48KB dynamic smem (immediate host API; idempotent every call)
    cudaFuncSetAttribute(k_gemm_t,      cudaFuncAttributeMaxDynamicSharedMemorySize, SMEM64);
    cudaFuncSetAttribute(k_gemm_xs,     cudaFuncAttributeMaxDynamicSharedMemorySize, SMEM128);
    cudaFuncSetAttribute(k_gemm_scores, cudaFuncAttributeMaxDynamicSharedMemorySize, SMEM128);
    cudaFuncSetAttribute(k_gemm_out,    cudaFuncAttributeMaxDynamicSharedMemorySize, SMEM64);

    k_prep_u<<<(2 * D_ * D_) / 256, 256>>>(U, S1, S2);
    k_transpose_y<<<dim3(D_ / 32, N_ / 32, B_), dim3(32, 8)>>>(y);
    k_pos<<<N_, 256>>>(coords, pos_emb, p_temp);

    k_gemm_t<<<dim3(D_ / 64, (B_ * N_) / 128), 256, SMEM64>>>(x, U);
    k_gemm_xs<<<dim3((2 * D_) / 128, (B_ * N_) / 128), 256, SMEM128>>>();
    k_gemm_scores<<<dim3(N_ / 128, N_ / 128, B_ * 2), 256, SMEM128>>>(y);

    k_mix<<<B_ * N_, 256>>>(gating, h_temp, heat);

    k_gemm_out<<<dim3(D_ / 64, N_ / 128, B_), 256, SMEM64>>>(out);
}